// round 1
// baseline (speedup 1.0000x reference)
#include <cuda_runtime.h>
#include <cuda_bf16.h>
#include <math.h>

// ---------------- problem constants ----------------
#define B    16
#define CMEL 80
#define CTXT 256
#define CATT 80
#define T1   800
#define T2   200

// ---------------- scratch (device globals, no allocation) ----------------
__device__ float g_k1[B * 512 * T2];   // key conv1 out (B,512,200)
__device__ float g_k [B * CATT * T2]; // key encoder out (B,80,200)
__device__ float g_q1[B * 160 * T1];   // query conv1 out (B,160,800)
__device__ float g_qm[B * CMEL * T1];  // query conv2 out (B,80,800)
__device__ float g_q [B * CATT * T1]; // query encoder out (B,80,800)

#define CK 16  // cin chunk

// ============================================================
// k=3 conv, pad=1:  y[b,co,t] = sum_{c,k} w[co,c,k]*x[b,c,t+k-1] + bias
// block = 128 threads, micro-tile 8co x 4t
// ============================================================
template<int TCO, int TT, int CIN, int RELU>
__global__ __launch_bounds__(128) void conv_k3_kernel(
    const float* __restrict__ x, const float* __restrict__ w,
    const float* __restrict__ bias, float* __restrict__ y,
    int T, int COUT)
{
    constexpr int COTHR = TCO / 8;
    constexpr int TTHR  = TT / 4;
    static_assert(COTHR * TTHR == 128, "block layout");
    constexpr int XROW = TT + 4;     // padded, 16B-aligned rows
    constexpr int WROW = CK * 3 + 1; // +1 to break bank conflicts

    __shared__ alignas(16) float Xs[CK * XROW];
    __shared__ float Ws[TCO * WROW];

    const int b   = blockIdx.z;
    const int co0 = blockIdx.y * TCO;
    const int t0  = blockIdx.x * TT;
    const int tid = threadIdx.x;
    const int ci  = tid / TTHR;   // 0..COTHR-1
    const int tj  = tid % TTHR;   // 0..TTHR-1

    const float* xb = x + (size_t)b * CIN * T;

    float acc[8][4];
    #pragma unroll
    for (int i = 0; i < 8; i++)
        #pragma unroll
        for (int j = 0; j < 4; j++) acc[i][j] = 0.f;

    for (int c0 = 0; c0 < CIN; c0 += CK) {
        // load X chunk with halo (TT+2 cols), zero-padded at sequence edges
        for (int idx = tid; idx < CK * (TT + 2); idx += 128) {
            int r = idx / (TT + 2), cc = idx % (TT + 2);
            int t = t0 + cc - 1;
            Xs[r * XROW + cc] = (t >= 0 && t < T) ? xb[(size_t)(c0 + r) * T + t] : 0.f;
        }
        // load W chunk: TCO rows x (CK*3) contiguous floats each
        for (int idx = tid; idx < TCO * CK * 3; idx += 128) {
            int r = idx / (CK * 3), cc = idx % (CK * 3);
            Ws[r * WROW + cc] = w[(size_t)(co0 + r) * CIN * 3 + (size_t)c0 * 3 + cc];
        }
        __syncthreads();

        #pragma unroll
        for (int ck = 0; ck < CK; ck++) {
            float xr[6];
            float4 xv = *(const float4*)&Xs[ck * XROW + tj * 4];
            xr[0] = xv.x; xr[1] = xv.y; xr[2] = xv.z; xr[3] = xv.w;
            xr[4] = Xs[ck * XROW + tj * 4 + 4];
            xr[5] = Xs[ck * XROW + tj * 4 + 5];
            #pragma unroll
            for (int i = 0; i < 8; i++) {
                const float* wr = &Ws[(ci * 8 + i) * WROW + ck * 3];
                float w0 = wr[0], w1 = wr[1], w2 = wr[2];
                #pragma unroll
                for (int j = 0; j < 4; j++)
                    acc[i][j] += w0 * xr[j] + w1 * xr[j + 1] + w2 * xr[j + 2];
            }
        }
        __syncthreads();
    }

    #pragma unroll
    for (int i = 0; i < 8; i++) {
        int co = co0 + ci * 8 + i;
        float bb = bias[co];
        #pragma unroll
        for (int j = 0; j < 4; j++) {
            int t = t0 + tj * 4 + j;
            if (t < T) {
                float v = acc[i][j] + bb;
                if (RELU) v = fmaxf(v, 0.f);
                y[((size_t)b * COUT + co) * T + t] = v;
            }
        }
    }
}

// ============================================================
// k=1 conv (GEMM): COUT fixed = 80.  block 256, micro 5co x 4t, TT=64
// ============================================================
template<int CIN, int RELU>
__global__ __launch_bounds__(256) void conv_k1_kernel(
    const float* __restrict__ x, const float* __restrict__ w,
    const float* __restrict__ bias, float* __restrict__ y, int T)
{
    __shared__ float Ws[80 * (CK + 1)];
    __shared__ alignas(16) float Xs[CK * 64];

    const int b  = blockIdx.y;
    const int t0 = blockIdx.x * 64;
    const int tid = threadIdx.x;
    const int ci = tid / 16;  // 0..15 -> 5 couts each
    const int tj = tid % 16;  // 0..15 -> 4 ts each

    const float* xb = x + (size_t)b * CIN * T;

    float acc[5][4];
    #pragma unroll
    for (int i = 0; i < 5; i++)
        #pragma unroll
        for (int j = 0; j < 4; j++) acc[i][j] = 0.f;

    for (int c0 = 0; c0 < CIN; c0 += CK) {
        for (int idx = tid; idx < 80 * CK; idx += 256) {
            int r = idx / CK, cc = idx % CK;
            Ws[r * (CK + 1) + cc] = w[(size_t)r * CIN + c0 + cc];
        }
        for (int idx = tid; idx < CK * 64; idx += 256) {
            int r = idx / 64, cc = idx % 64;
            int t = t0 + cc;
            Xs[r * 64 + cc] = (t < T) ? xb[(size_t)(c0 + r) * T + t] : 0.f;
        }
        __syncthreads();

        #pragma unroll
        for (int ck = 0; ck < CK; ck++) {
            float4 xv = *(const float4*)&Xs[ck * 64 + tj * 4];
            #pragma unroll
            for (int i = 0; i < 5; i++) {
                float wv = Ws[(ci * 5 + i) * (CK + 1) + ck];
                acc[i][0] += wv * xv.x;
                acc[i][1] += wv * xv.y;
                acc[i][2] += wv * xv.z;
                acc[i][3] += wv * xv.w;
            }
        }
        __syncthreads();
    }

    #pragma unroll
    for (int i = 0; i < 5; i++) {
        int co = ci * 5 + i;
        float bb = bias[co];
        #pragma unroll
        for (int j = 0; j < 4; j++) {
            int t = t0 + tj * 4 + j;
            if (t < T) {
                float v = acc[i][j] + bb;
                if (RELU) v = fmaxf(v, 0.f);
                y[((size_t)b * 80 + co) * T + t] = v;
            }
        }
    }
}

// ============================================================
// Attention: dist -> log_softmax over T2 -> + log(prior+1e-8)
// block per (b, 32 t1 rows): warp handles 4 rows; lane covers 7 t2 slots.
// ============================================================
#define KROW 224  // padded T2
__global__ __launch_bounds__(256) void attn_kernel(
    const float* __restrict__ q, const float* __restrict__ k,
    const float* __restrict__ prior, float* __restrict__ out)
{
    extern __shared__ float sm[];
    float* ks  = sm;                 // 80 * 224
    float* qs  = ks + 80 * KROW;     // 80 * 32
    float* k2s = qs + 80 * 32;       // 224
    float* q2s = k2s + KROW;         // 32

    const int b   = blockIdx.y;
    const int t10 = blockIdx.x * 32;
    const int tid = threadIdx.x;

    const float* kb = k + (size_t)b * CATT * T2;
    const float* qb = q + (size_t)b * CATT * T1;

    for (int idx = tid; idx < 80 * KROW; idx += 256) {
        int c = idx / KROW, t = idx % KROW;
        ks[idx] = (t < T2) ? kb[(size_t)c * T2 + t] : 0.f;
    }
    for (int idx = tid; idx < 80 * 32; idx += 256) {
        int c = idx / 32, i = idx % 32;
        qs[idx] = qb[(size_t)c * T1 + t10 + i];
    }
    __syncthreads();

    if (tid < KROW) {
        float s = 0.f;
        #pragma unroll 8
        for (int c = 0; c < 80; c++) { float v = ks[c * KROW + tid]; s += v * v; }
        k2s[tid] = s;
    } else {
        int i = tid - KROW;
        if (i < 32) {
            float s = 0.f;
            #pragma unroll 8
            for (int c = 0; c < 80; c++) { float v = qs[c * 32 + i]; s += v * v; }
            q2s[i] = s;
        }
    }
    __syncthreads();

    const int warp = tid / 32;
    const int lane = tid % 32;

    float dot[4][7];
    #pragma unroll
    for (int i = 0; i < 4; i++)
        #pragma unroll
        for (int j = 0; j < 7; j++) dot[i][j] = 0.f;

    #pragma unroll 4
    for (int c = 0; c < 80; c++) {
        float qv[4];
        #pragma unroll
        for (int i = 0; i < 4; i++) qv[i] = qs[c * 32 + warp * 4 + i];
        float kv[7];
        #pragma unroll
        for (int j = 0; j < 7; j++) kv[j] = ks[c * KROW + lane + 32 * j];
        #pragma unroll
        for (int i = 0; i < 4; i++)
            #pragma unroll
            for (int j = 0; j < 7; j++) dot[i][j] += qv[i] * kv[j];
    }

    const bool last_valid = (lane + 192) < T2;

    #pragma unroll
    for (int i = 0; i < 4; i++) {
        int r  = warp * 4 + i;
        int t1 = t10 + r;
        float q2 = q2s[r];
        float xv[7];
        #pragma unroll
        for (int j = 0; j < 7; j++) {
            int t2 = lane + 32 * j;
            bool valid = (j < 6) || last_valid;
            xv[j] = valid ? (-0.0005f * (q2 + k2s[t2] - 2.f * dot[i][j])) : -1e30f;
        }
        // max over the row
        float m = xv[0];
        #pragma unroll
        for (int j = 1; j < 7; j++) m = fmaxf(m, xv[j]);
        #pragma unroll
        for (int off = 16; off; off >>= 1)
            m = fmaxf(m, __shfl_xor_sync(0xFFFFFFFFu, m, off));
        // sum exp
        float s = 0.f;
        #pragma unroll
        for (int j = 0; j < 7; j++) {
            bool valid = (j < 6) || last_valid;
            if (valid) s += __expf(xv[j] - m);
        }
        #pragma unroll
        for (int off = 16; off; off >>= 1)
            s += __shfl_xor_sync(0xFFFFFFFFu, s, off);
        float lse = m + logf(s);

        const float* pr = prior + ((size_t)b * T1 + t1) * T2;
        float* ob = out + ((size_t)b * T1 + t1) * T2;
        #pragma unroll
        for (int j = 0; j < 7; j++) {
            int t2 = lane + 32 * j;
            bool valid = (j < 6) || last_valid;
            if (valid)
                ob[t2] = xv[j] - lse + logf(pr[t2] + 1e-8f);
        }
    }
}

// ============================================================
// launch
// ============================================================
extern "C" void kernel_launch(void* const* d_in, const int* in_sizes, int n_in,
                              void* d_out, int out_size)
{
    const float* queries = (const float*)d_in[0];   // (16,80,800)
    const float* keys    = (const float*)d_in[1];   // (16,256,200)
    const float* prior   = (const float*)d_in[2];   // (16,800,200)
    const float* kw1 = (const float*)d_in[3];       // (512,256,3)
    const float* kb1 = (const float*)d_in[4];
    const float* kw2 = (const float*)d_in[5];       // (80,512,1)
    const float* kb2 = (const float*)d_in[6];
    const float* qw1 = (const float*)d_in[7];       // (160,80,3)
    const float* qb1 = (const float*)d_in[8];
    const float* qw2 = (const float*)d_in[9];       // (80,160,1)
    const float* qb2 = (const float*)d_in[10];
    const float* qw3 = (const float*)d_in[11];      // (80,80,1)
    const float* qb3 = (const float*)d_in[12];
    float* out = (float*)d_out;

    float *p_k1, *p_k, *p_q1, *p_qm, *p_q;
    cudaGetSymbolAddress((void**)&p_k1, g_k1);
    cudaGetSymbolAddress((void**)&p_k,  g_k);
    cudaGetSymbolAddress((void**)&p_q1, g_q1);
    cudaGetSymbolAddress((void**)&p_qm, g_qm);
    cudaGetSymbolAddress((void**)&p_q,  g_q);

    const int ATTN_SMEM = (80 * KROW + 80 * 32 + KROW + 32) * 4;
    cudaFuncSetAttribute(attn_kernel, cudaFuncAttributeMaxDynamicSharedMemorySize, ATTN_SMEM);

    // ---- key encoder ----
    // conv1: 256 -> 512, k3, ReLU; tile 128co x 32t
    conv_k3_kernel<128, 32, 256, 1><<<dim3((T2 + 31) / 32, 512 / 128, B), 128>>>(
        keys, kw1, kb1, p_k1, T2, 512);
    // conv2: 512 -> 80, k1
    conv_k1_kernel<512, 0><<<dim3((T2 + 63) / 64, B), 256>>>(p_k1, kw2, kb2, p_k, T2);

    // ---- query encoder ----
    // conv1: 80 -> 160, k3, ReLU; tile 32co x 128t
    conv_k3_kernel<32, 128, 80, 1><<<dim3((T1 + 127) / 128, 160 / 32, B), 128>>>(
        queries, qw1, qb1, p_q1, T1, 160);
    // conv2: 160 -> 80, k1, ReLU
    conv_k1_kernel<160, 1><<<dim3((T1 + 63) / 64, B), 256>>>(p_q1, qw2, qb2, p_qm, T1);
    // conv3: 80 -> 80, k1
    conv_k1_kernel<80, 0><<<dim3((T1 + 63) / 64, B), 256>>>(p_qm, qw3, qb3, p_q, T1);

    // ---- attention ----
    attn_kernel<<<dim3(T1 / 32, B), 256, ATTN_SMEM>>>(p_q, p_k, prior, out);
}

// round 3
// speedup vs baseline: 1.5461x; 1.5461x over previous
#include <cuda_runtime.h>
#include <math.h>

// ---------------- problem constants ----------------
#define B    16
#define T1   800
#define T2   200
#define CATT 80

typedef unsigned long long u64;

__device__ __forceinline__ u64 pk2(float lo, float hi) {
    u64 r; asm("mov.b64 %0,{%1,%2};" : "=l"(r) : "f"(lo), "f"(hi)); return r;
}
__device__ __forceinline__ void upk2(u64 v, float& lo, float& hi) {
    asm("mov.b64 {%0,%1},%2;" : "=f"(lo), "=f"(hi) : "l"(v));
}
__device__ __forceinline__ void ffma2(u64& d, u64 a, u64 b) {
    asm("fma.rn.f32x2 %0,%1,%2,%0;" : "+l"(d) : "l"(a), "l"(b));
}

// ---------------- scratch ----------------
__device__ float g_k1[B * 512 * T2];   // key conv1 out
__device__ float g_k [B * CATT * T2];  // key encoder out
__device__ float g_q1[B * 160 * T1];   // query conv1 out
__device__ float g_q [B * CATT * T1];  // query encoder out

// ============================================================
// k=3 conv, pad=1, f32x2, double-buffered.
// 128 threads, micro-tile 8co x 4t. (TCO/8)*(TT/4) == 128.
// ============================================================
template<int TCO, int TT, int CIN, int RELU>
__global__ __launch_bounds__(128) void conv_k3_x2(
    const float* __restrict__ x, const float* __restrict__ w,
    const float* __restrict__ bias, float* __restrict__ y,
    int T, int COUT)
{
    constexpr int CK   = 16;
    constexpr int XROW = TT + 4;
    constexpr int NC   = CIN / CK;
    constexpr int COTHR = TCO / 8;
    constexpr int TTHR  = TT / 4;
    static_assert(COTHR * TTHR == 128, "layout");
    constexpr int XTOT = CK * (TT + 2);
    constexpr int WTOT = TCO * CK * 3;      // float2 elems
    constexpr int XLD  = (XTOT + 127) / 128;
    constexpr int WLD  = WTOT / 128;
    static_assert(WTOT % 128 == 0, "wld");

    extern __shared__ char smraw[];
    float*  Xs = (float*)smraw;                                  // 2 * CK*XROW
    float2* Ws = (float2*)(smraw + 2 * CK * XROW * sizeof(float)); // 2 * WTOT

    const int b   = blockIdx.z;
    const int co0 = blockIdx.y * TCO;
    const int t0  = blockIdx.x * TT;
    const int tid = threadIdx.x;
    const int ci  = tid / TTHR;
    const int tj  = tid % TTHR;
    const float* xb = x + (size_t)b * CIN * T;

    u64 acc[8][2];
    #pragma unroll
    for (int i = 0; i < 8; i++) { acc[i][0] = 0ull; acc[i][1] = 0ull; }

    float xr_[XLD], wr_[WLD];

    // prefetch chunk 0
    #pragma unroll
    for (int i = 0; i < XLD; i++) {
        int e = tid + i * 128;
        if (e < XTOT) {
            int r = e / (TT + 2), cc = e % (TT + 2);
            int t = t0 + cc - 1;
            xr_[i] = (t >= 0 && t < T) ? xb[(size_t)r * T + t] : 0.f;
        }
    }
    #pragma unroll
    for (int i = 0; i < WLD; i++) {
        int e = tid + i * 128;
        int r = e / (CK * 3), cc = e % (CK * 3);
        wr_[i] = w[(size_t)(co0 + r) * (CIN * 3) + cc];
    }
    // sts chunk 0
    #pragma unroll
    for (int i = 0; i < XLD; i++) {
        int e = tid + i * 128;
        if (e < XTOT) { int r = e / (TT + 2), cc = e % (TT + 2); Xs[r * XROW + cc] = xr_[i]; }
    }
    #pragma unroll
    for (int i = 0; i < WLD; i++) {
        int e = tid + i * 128;
        Ws[e] = make_float2(wr_[i], wr_[i]);
    }
    __syncthreads();

    for (int c = 0; c < NC; c++) {
        if (c + 1 < NC) {
            const int c0 = (c + 1) * CK;
            #pragma unroll
            for (int i = 0; i < XLD; i++) {
                int e = tid + i * 128;
                if (e < XTOT) {
                    int r = e / (TT + 2), cc = e % (TT + 2);
                    int t = t0 + cc - 1;
                    xr_[i] = (t >= 0 && t < T) ? xb[(size_t)(c0 + r) * T + t] : 0.f;
                }
            }
            #pragma unroll
            for (int i = 0; i < WLD; i++) {
                int e = tid + i * 128;
                int r = e / (CK * 3), cc = e % (CK * 3);
                wr_[i] = w[(size_t)(co0 + r) * (CIN * 3) + (size_t)c0 * 3 + cc];
            }
        }
        const float*  X = Xs + (c & 1) * CK * XROW;
        const float2* W = Ws + (c & 1) * WTOT;
        #pragma unroll
        for (int ck = 0; ck < CK; ck++) {
            const float* xp = X + ck * XROW + tj * 4;
            float4 x4 = *(const float4*)xp;
            float  x5 = xp[4], x6 = xp[5];
            u64 p0 = pk2(x4.x, x4.y), p1 = pk2(x4.y, x4.z), p2 = pk2(x4.z, x4.w);
            u64 p3 = pk2(x4.w, x5),   p4 = pk2(x5, x6);
            #pragma unroll
            for (int i = 0; i < 8; i++) {
                const u64* wp = (const u64*)(W + (size_t)(ci * 8 + i) * (CK * 3) + ck * 3);
                u64 w0 = wp[0], w1 = wp[1], w2 = wp[2];
                ffma2(acc[i][0], p0, w0); ffma2(acc[i][1], p2, w0);
                ffma2(acc[i][0], p1, w1); ffma2(acc[i][1], p3, w1);
                ffma2(acc[i][0], p2, w2); ffma2(acc[i][1], p4, w2);
            }
        }
        if (c + 1 < NC) {
            __syncthreads();
            float*  Xd = Xs + ((c + 1) & 1) * CK * XROW;
            float2* Wd = Ws + ((c + 1) & 1) * WTOT;
            #pragma unroll
            for (int i = 0; i < XLD; i++) {
                int e = tid + i * 128;
                if (e < XTOT) { int r = e / (TT + 2), cc = e % (TT + 2); Xd[r * XROW + cc] = xr_[i]; }
            }
            #pragma unroll
            for (int i = 0; i < WLD; i++) {
                int e = tid + i * 128;
                Wd[e] = make_float2(wr_[i], wr_[i]);
            }
            __syncthreads();
        }
    }

    #pragma unroll
    for (int i = 0; i < 8; i++) {
        int co = co0 + ci * 8 + i;
        float bb = bias[co];
        float v0, v1, v2, v3;
        upk2(acc[i][0], v0, v1);
        upk2(acc[i][1], v2, v3);
        float v[4] = {v0, v1, v2, v3};
        #pragma unroll
        for (int j = 0; j < 4; j++) {
            int t = t0 + tj * 4 + j;
            if (t < T) {
                float o = v[j] + bb;
                if (RELU) o = fmaxf(o, 0.f);
                y[((size_t)b * COUT + co) * T + t] = o;
            }
        }
    }
}

// ============================================================
// key conv2: k=1, 512 -> 80, T=200.  f32x2, double-buffered.
// 128 threads, tile 80co x 32t, micro 5co x 4t.
// ============================================================
__global__ __launch_bounds__(128) void key_conv2_x2(
    const float* __restrict__ x, const float* __restrict__ w,
    const float* __restrict__ bias, float* __restrict__ y)
{
    constexpr int CIN = 512, CK = 32, NC = CIN / CK, TTILE = 32;
    constexpr int WTOT = 80 * CK;        // float2 elems
    constexpr int XTOT = CK * TTILE;
    constexpr int WLD = WTOT / 128;      // 20
    constexpr int XLD = XTOT / 128;      // 8

    extern __shared__ char smraw[];
    float2* Ws = (float2*)smraw;                              // 2*WTOT
    float*  Xs = (float*)(smraw + 2 * WTOT * sizeof(float2)); // 2*XTOT

    const int b  = blockIdx.y;
    const int t0 = blockIdx.x * TTILE;
    const int tid = threadIdx.x, ci = tid / 8, tj = tid % 8;
    const float* xb = x + (size_t)b * CIN * T2;

    u64 acc[5][2];
    #pragma unroll
    for (int i = 0; i < 5; i++) { acc[i][0] = 0ull; acc[i][1] = 0ull; }

    float wr_[WLD], xr_[XLD];
    #pragma unroll
    for (int i = 0; i < WLD; i++) {
        int e = tid + i * 128; int r = e / CK, cc = e % CK;
        wr_[i] = w[(size_t)r * CIN + cc];
    }
    #pragma unroll
    for (int i = 0; i < XLD; i++) {
        int e = tid + i * 128; int r = e / TTILE, cc = e % TTILE;
        int t = t0 + cc;
        xr_[i] = (t < T2) ? xb[(size_t)r * T2 + t] : 0.f;
    }
    #pragma unroll
    for (int i = 0; i < WLD; i++) { int e = tid + i * 128; Ws[e] = make_float2(wr_[i], wr_[i]); }
    #pragma unroll
    for (int i = 0; i < XLD; i++) { int e = tid + i * 128; Xs[e] = xr_[i]; }
    __syncthreads();

    for (int c = 0; c < NC; c++) {
        if (c + 1 < NC) {
            const int c0 = (c + 1) * CK;
            #pragma unroll
            for (int i = 0; i < WLD; i++) {
                int e = tid + i * 128; int r = e / CK, cc = e % CK;
                wr_[i] = w[(size_t)r * CIN + c0 + cc];
            }
            #pragma unroll
            for (int i = 0; i < XLD; i++) {
                int e = tid + i * 128; int r = e / TTILE, cc = e % TTILE;
                int t = t0 + cc;
                xr_[i] = (t < T2) ? xb[(size_t)(c0 + r) * T2 + t] : 0.f;
            }
        }
        const float2* W = Ws + (c & 1) * WTOT;
        const float*  X = Xs + (c & 1) * XTOT;
        #pragma unroll
        for (int ck = 0; ck < CK; ck += 2) {
            float4 xa = *(const float4*)(X + ck * TTILE + tj * 4);
            float4 xc = *(const float4*)(X + (ck + 1) * TTILE + tj * 4);
            u64 a0 = pk2(xa.x, xa.y), a1 = pk2(xa.z, xa.w);
            u64 b0 = pk2(xc.x, xc.y), b1 = pk2(xc.z, xc.w);
            #pragma unroll
            for (int i = 0; i < 5; i++) {
                float4 wv = *(const float4*)(W + (size_t)(ci * 5 + i) * CK + ck);
                u64 w0 = pk2(wv.x, wv.y), w1 = pk2(wv.z, wv.w);
                ffma2(acc[i][0], a0, w0); ffma2(acc[i][1], a1, w0);
                ffma2(acc[i][0], b0, w1); ffma2(acc[i][1], b1, w1);
            }
        }
        if (c + 1 < NC) {
            __syncthreads();
            float2* Wd = Ws + ((c + 1) & 1) * WTOT;
            float*  Xd = Xs + ((c + 1) & 1) * XTOT;
            #pragma unroll
            for (int i = 0; i < WLD; i++) { int e = tid + i * 128; Wd[e] = make_float2(wr_[i], wr_[i]); }
            #pragma unroll
            for (int i = 0; i < XLD; i++) { int e = tid + i * 128; Xd[e] = xr_[i]; }
            __syncthreads();
        }
    }

    #pragma unroll
    for (int i = 0; i < 5; i++) {
        int co = ci * 5 + i;
        float bb = bias[co];
        float v0, v1, v2, v3;
        upk2(acc[i][0], v0, v1); upk2(acc[i][1], v2, v3);
        float v[4] = {v0, v1, v2, v3};
        #pragma unroll
        for (int j = 0; j < 4; j++) {
            int t = t0 + tj * 4 + j;
            if (t < T2) y[((size_t)b * 80 + co) * T2 + t] = v[j] + bb;
        }
    }
}

// ============================================================
// fused query conv2 (160->80 k1 ReLU) + conv3 (80->80 k1)
// 256 threads, tile 64t, micro 5co x 4t.
// ============================================================
__global__ __launch_bounds__(256) void qconv23_x2(
    const float* __restrict__ x,
    const float* __restrict__ w2, const float* __restrict__ b2,
    const float* __restrict__ w3, const float* __restrict__ b3,
    float* __restrict__ y)
{
    constexpr int CIN = 160, CK = 32, NC = CIN / CK, TTILE = 64;
    constexpr int W2TOT = 80 * CK;   // float2 elems per chunk

    extern __shared__ char smraw[];
    float*  Xs  = (float*)smraw;                                  // 160*64
    float2* W2s = (float2*)(smraw + CIN * TTILE * sizeof(float)); // 2*W2TOT
    float*  Hs  = (float*)((char*)W2s + 2 * W2TOT * sizeof(float2)); // 80*64
    float2* W3s = (float2*)((char*)Hs + 80 * TTILE * sizeof(float)); // 6400

    const int b  = blockIdx.y;
    const int t0 = blockIdx.x * TTILE;
    const int tid = threadIdx.x, ci = tid / 16, tj = tid % 16;
    const float* xb = x + (size_t)b * CIN * T1;

    // load full X tile + full W3 (duplicated)
    #pragma unroll
    for (int i = 0; i < CIN * TTILE / 256; i++) {
        int e = tid + i * 256; int r = e / TTILE, cc = e % TTILE;
        int t = t0 + cc;
        Xs[e] = (t < T1) ? xb[(size_t)r * T1 + t] : 0.f;
    }
    #pragma unroll
    for (int i = 0; i < 6400 / 256; i++) {
        int e = tid + i * 256; float v = w3[e];
        W3s[e] = make_float2(v, v);
    }
    // W2 chunk 0
    constexpr int W2LD = W2TOT / 256;  // 10
    float wr_[W2LD];
    #pragma unroll
    for (int i = 0; i < W2LD; i++) {
        int e = tid + i * 256; int r = e / CK, cc = e % CK;
        wr_[i] = w2[(size_t)r * CIN + cc];
    }
    #pragma unroll
    for (int i = 0; i < W2LD; i++) { int e = tid + i * 256; W2s[e] = make_float2(wr_[i], wr_[i]); }
    __syncthreads();

    u64 acc[5][2];
    #pragma unroll
    for (int i = 0; i < 5; i++) { acc[i][0] = 0ull; acc[i][1] = 0ull; }

    for (int c = 0; c < NC; c++) {
        if (c + 1 < NC) {
            const int c0 = (c + 1) * CK;
            #pragma unroll
            for (int i = 0; i < W2LD; i++) {
                int e = tid + i * 256; int r = e / CK, cc = e % CK;
                wr_[i] = w2[(size_t)r * CIN + c0 + cc];
            }
        }
        const float2* W = W2s + (c & 1) * W2TOT;
        #pragma unroll
        for (int ck = 0; ck < CK; ck += 2) {
            int cin = c * CK + ck;
            float4 xa = *(const float4*)(Xs + (size_t)cin * TTILE + tj * 4);
            float4 xc = *(const float4*)(Xs + (size_t)(cin + 1) * TTILE + tj * 4);
            u64 a0 = pk2(xa.x, xa.y), a1 = pk2(xa.z, xa.w);
            u64 b0 = pk2(xc.x, xc.y), b1 = pk2(xc.z, xc.w);
            #pragma unroll
            for (int i = 0; i < 5; i++) {
                float4 wv = *(const float4*)(W + (size_t)(ci * 5 + i) * CK + ck);
                u64 w0 = pk2(wv.x, wv.y), w1 = pk2(wv.z, wv.w);
                ffma2(acc[i][0], a0, w0); ffma2(acc[i][1], a1, w0);
                ffma2(acc[i][0], b0, w1); ffma2(acc[i][1], b1, w1);
            }
        }
        if (c + 1 < NC) {
            __syncthreads();
            float2* Wd = W2s + ((c + 1) & 1) * W2TOT;
            #pragma unroll
            for (int i = 0; i < W2LD; i++) { int e = tid + i * 256; Wd[e] = make_float2(wr_[i], wr_[i]); }
            __syncthreads();
        }
    }

    // h = relu(acc + b2) -> smem
    #pragma unroll
    for (int i = 0; i < 5; i++) {
        int co = ci * 5 + i;
        float bb = b2[co];
        float v0, v1, v2, v3;
        upk2(acc[i][0], v0, v1); upk2(acc[i][1], v2, v3);
        float4 hv;
        hv.x = fmaxf(v0 + bb, 0.f); hv.y = fmaxf(v1 + bb, 0.f);
        hv.z = fmaxf(v2 + bb, 0.f); hv.w = fmaxf(v3 + bb, 0.f);
        *(float4*)(Hs + (size_t)co * TTILE + tj * 4) = hv;
    }
    __syncthreads();

    // phase 2: 80 -> 80
    u64 acc2_[5][2];
    #pragma unroll
    for (int i = 0; i < 5; i++) { acc2_[i][0] = 0ull; acc2_[i][1] = 0ull; }
    #pragma unroll 8
    for (int cc2 = 0; cc2 < 80; cc2 += 2) {
        float4 xa = *(const float4*)(Hs + (size_t)cc2 * TTILE + tj * 4);
        float4 xc = *(const float4*)(Hs + (size_t)(cc2 + 1) * TTILE + tj * 4);
        u64 a0 = pk2(xa.x, xa.y), a1 = pk2(xa.z, xa.w);
        u64 b0 = pk2(xc.x, xc.y), b1 = pk2(xc.z, xc.w);
        #pragma unroll
        for (int i = 0; i < 5; i++) {
            float4 wv = *(const float4*)(W3s + (size_t)(ci * 5 + i) * 80 + cc2);
            u64 w0 = pk2(wv.x, wv.y), w1 = pk2(wv.z, wv.w);
            ffma2(acc2_[i][0], a0, w0); ffma2(acc2_[i][1], a1, w0);
            ffma2(acc2_[i][0], b0, w1); ffma2(acc2_[i][1], b1, w1);
        }
    }

    #pragma unroll
    for (int i = 0; i < 5; i++) {
        int co = ci * 5 + i;
        float bb = b3[co];
        float v0, v1, v2, v3;
        upk2(acc2_[i][0], v0, v1); upk2(acc2_[i][1], v2, v3);
        float v[4] = {v0, v1, v2, v3};
        #pragma unroll
        for (int j = 0; j < 4; j++) {
            int t = t0 + tj * 4 + j;
            if (t < T1) y[((size_t)b * 80 + co) * T1 + t] = v[j] + bb;
        }
    }
}

// ============================================================
// Attention: dist -> log_softmax over T2 -> + log(prior+1e-8)
// ============================================================
#define KROW 224
__global__ __launch_bounds__(256) void attn_kernel(
    const float* __restrict__ q, const float* __restrict__ k,
    const float* __restrict__ prior, float* __restrict__ out)
{
    extern __shared__ float sm[];
    float* ks  = sm;                 // 80 * 224
    float* qs  = ks + 80 * KROW;     // 80 * 32
    float* k2s = qs + 80 * 32;       // 224
    float* q2s = k2s + KROW;         // 32

    const int b   = blockIdx.y;
    const int t10 = blockIdx.x * 32;
    const int tid = threadIdx.x;

    const float* kb = k + (size_t)b * CATT * T2;
    const float* qb = q + (size_t)b * CATT * T1;

    for (int idx = tid; idx < 80 * KROW; idx += 256) {
        int c = idx / KROW, t = idx % KROW;
        ks[idx] = (t < T2) ? kb[(size_t)c * T2 + t] : 0.f;
    }
    for (int idx = tid; idx < 80 * 32; idx += 256) {
        int c = idx / 32, i = idx % 32;
        qs[idx] = qb[(size_t)c * T1 + t10 + i];
    }
    __syncthreads();

    if (tid < KROW) {
        float s = 0.f;
        #pragma unroll 8
        for (int c = 0; c < 80; c++) { float v = ks[c * KROW + tid]; s += v * v; }
        k2s[tid] = s;
    } else {
        int i = tid - KROW;
        if (i < 32) {
            float s = 0.f;
            #pragma unroll 8
            for (int c = 0; c < 80; c++) { float v = qs[c * 32 + i]; s += v * v; }
            q2s[i] = s;
        }
    }
    __syncthreads();

    const int warp = tid / 32;
    const int lane = tid % 32;

    float dot[4][7];
    #pragma unroll
    for (int i = 0; i < 4; i++)
        #pragma unroll
        for (int j = 0; j < 7; j++) dot[i][j] = 0.f;

    #pragma unroll 4
    for (int c = 0; c < 80; c++) {
        float4 q4 = *(const float4*)&qs[c * 32 + warp * 4];
        float qv[4] = {q4.x, q4.y, q4.z, q4.w};
        float kv[7];
        #pragma unroll
        for (int j = 0; j < 7; j++) kv[j] = ks[c * KROW + lane + 32 * j];
        #pragma unroll
        for (int i = 0; i < 4; i++)
            #pragma unroll
            for (int j = 0; j < 7; j++) dot[i][j] += qv[i] * kv[j];
    }

    const bool last_valid = (lane + 192) < T2;

    #pragma unroll
    for (int i = 0; i < 4; i++) {
        int r  = warp * 4 + i;
        int t1 = t10 + r;
        float q2 = q2s[r];
        float xv[7];
        #pragma unroll
        for (int j = 0; j < 7; j++) {
            int t2 = lane + 32 * j;
            bool valid = (j < 6) || last_valid;
            xv[j] = valid ? (-0.0005f * (q2 + k2s[t2] - 2.f * dot[i][j])) : -1e30f;
        }
        float m = xv[0];
        #pragma unroll
        for (int j = 1; j < 7; j++) m = fmaxf(m, xv[j]);
        #pragma unroll
        for (int off = 16; off; off >>= 1)
            m = fmaxf(m, __shfl_xor_sync(0xFFFFFFFFu, m, off));
        float s = 0.f;
        #pragma unroll
        for (int j = 0; j < 7; j++) {
            bool valid = (j < 6) || last_valid;
            if (valid) s += __expf(xv[j] - m);
        }
        #pragma unroll
        for (int off = 16; off; off >>= 1)
            s += __shfl_xor_sync(0xFFFFFFFFu, s, off);
        float lse = m + __logf(s);

        const float* pr = prior + ((size_t)b * T1 + t1) * T2;
        float* ob = out + ((size_t)b * T1 + t1) * T2;
        #pragma unroll
        for (int j = 0; j < 7; j++) {
            int t2 = lane + 32 * j;
            bool valid = (j < 6) || last_valid;
            if (valid)
                ob[t2] = xv[j] - lse + __logf(pr[t2] + 1e-8f);
        }
    }
}

// ============================================================
// launch
// ============================================================
extern "C" void kernel_launch(void* const* d_in, const int* in_sizes, int n_in,
                              void* d_out, int out_size)
{
    const float* queries = (const float*)d_in[0];
    const float* keys    = (const float*)d_in[1];
    const float* prior   = (const float*)d_in[2];
    const float* kw1 = (const float*)d_in[3];
    const float* kb1 = (const float*)d_in[4];
    const float* kw2 = (const float*)d_in[5];
    const float* kb2 = (const float*)d_in[6];
    const float* qw1 = (const float*)d_in[7];
    const float* qb1 = (const float*)d_in[8];
    const float* qw2 = (const float*)d_in[9];
    const float* qb2 = (const float*)d_in[10];
    const float* qw3 = (const float*)d_in[11];
    const float* qb3 = (const float*)d_in[12];
    float* out = (float*)d_out;

    float *p_k1, *p_k, *p_q1, *p_q;
    cudaGetSymbolAddress((void**)&p_k1, g_k1);
    cudaGetSymbolAddress((void**)&p_k,  g_k);
    cudaGetSymbolAddress((void**)&p_q1, g_q1);
    cudaGetSymbolAddress((void**)&p_q,  g_q);

    // smem sizes
    const int SM_KEYK3 = 2 * 16 * 68 * 4 + 2 * 64 * 48 * 8;        // 57856
    const int SM_QK3   = 2 * 16 * 132 * 4 + 2 * 32 * 48 * 8;       // 41472
    const int SM_KEYK1 = 2 * (80 * 32) * 8 + 2 * (32 * 32) * 4;    // 49152
    const int SM_QF    = 160 * 64 * 4 + 2 * (80 * 32) * 8 + 80 * 64 * 4 + 6400 * 8; // 153600
    const int SM_ATTN  = (80 * KROW + 80 * 32 + KROW + 32) * 4;    // 82944

    cudaFuncSetAttribute(conv_k3_x2<64, 64, 256, 1>, cudaFuncAttributeMaxDynamicSharedMemorySize, SM_KEYK3);
    cudaFuncSetAttribute(conv_k3_x2<32, 128, 80, 1>, cudaFuncAttributeMaxDynamicSharedMemorySize, SM_QK3);
    cudaFuncSetAttribute(key_conv2_x2, cudaFuncAttributeMaxDynamicSharedMemorySize, SM_KEYK1);
    cudaFuncSetAttribute(qconv23_x2, cudaFuncAttributeMaxDynamicSharedMemorySize, SM_QF);
    cudaFuncSetAttribute(attn_kernel, cudaFuncAttributeMaxDynamicSharedMemorySize, SM_ATTN);

    // key conv1: 256 -> 512, k3, ReLU
    conv_k3_x2<64, 64, 256, 1><<<dim3((T2 + 63) / 64, 512 / 64, B), 128, SM_KEYK3>>>(
        keys, kw1, kb1, p_k1, T2, 512);
    // query conv1: 80 -> 160, k3, ReLU
    conv_k3_x2<32, 128, 80, 1><<<dim3((T1 + 127) / 128, 160 / 32, B), 128, SM_QK3>>>(
        queries, qw1, qb1, p_q1, T1, 160);
    // key conv2: 512 -> 80, k1
    key_conv2_x2<<<dim3((T2 + 31) / 32, B), 128, SM_KEYK1>>>(p_k1, kw2, kb2, p_k);
    // query conv2+3 fused
    qconv23_x2<<<dim3((T1 + 63) / 64, B), 256, SM_QF>>>(p_q1, qw2, qb2, qw3, qb3, p_q);
    // attention
    attn_kernel<<<dim3(T1 / 32, B), 256, SM_ATTN>>>(p_q, p_k, prior, out);
}